// round 14
// baseline (speedup 1.0000x reference)
#include <cuda_runtime.h>
#include <cuda_fp16.h>
#include <cstdint>

// ---------------------------------------------------------------------------
// Problem constants
// ---------------------------------------------------------------------------
#define B_ 4
#define N_ 4096
#define M_ 4096
#define C_ 512
#define R_ (B_ * N_)                     // 16384 rows
static const long NM_ = (long)N_ * M_;   // 16,777,216 per batch

// ---------------------------------------------------------------------------
// Champion GEMM tiling (R7 = 831us): CTA 128x128, 8 warps (2Mx4N grid),
// warp tile 64x32, BK=64, 3-stage cp.async, 2 CTAs/SM.
// ---------------------------------------------------------------------------
#define BK 64
#define STAGES 3
#define ROWB 144                  // 64 fp16 = 128B + 16B pad (conflict-free)
#define TILE_B (128 * ROWB)       // 18432 B per operand tile
#define STAGE_B (2 * TILE_B)      // A, B
#define SMEM_B (STAGES * STAGE_B) // 110592 B

__device__ __forceinline__ uint32_t smem_u32(const void* p) {
    uint32_t a;
    asm("{ .reg .u64 t; cvta.to.shared.u64 t, %1; cvt.u32.u64 %0, t; }" : "=r"(a) : "l"(p));
    return a;
}

#define LDSM4(r, addr) \
    asm volatile("ldmatrix.sync.aligned.m8n8.x4.shared.b16 {%0,%1,%2,%3}, [%4];" \
                 : "=r"((r)[0]), "=r"((r)[1]), "=r"((r)[2]), "=r"((r)[3]) : "r"(addr))

#define MMA(dd, aa, b0, b1) \
    asm volatile("mma.sync.aligned.m16n8k16.row.col.f32.f16.f16.f32 " \
                 "{%0,%1,%2,%3}, {%4,%5,%6,%7}, {%8,%9}, {%0,%1,%2,%3};" \
                 : "+f"((dd)[0]), "+f"((dd)[1]), "+f"((dd)[2]), "+f"((dd)[3]) \
                 : "r"((aa)[0]), "r"((aa)[1]), "r"((aa)[2]), "r"((aa)[3]), \
                   "r"(b0), "r"(b1))

#define CP16(saddr, gptr) \
    asm volatile("cp.async.cg.shared.global [%0], [%1], 16;" :: "r"(saddr), "l"(gptr))

#define CP_COMMIT() asm volatile("cp.async.commit_group;" ::: "memory")
#define CP_WAIT(n)  asm volatile("cp.async.wait_group %0;" :: "n"(n) : "memory")

// ---------------------------------------------------------------------------
// Scratch
// ---------------------------------------------------------------------------
__device__ __half g_rgb[R_ * C_];
__device__ __half g_dep[R_ * C_];
__device__ __half g_wt[3 * C_ * C_];             // W^T for q,k,v: [co][c]
__device__ __half g_q[R_ * C_];
__device__ __half g_k[R_ * C_];
__device__ __half g_vt[(long)B_ * C_ * M_];      // V^T per batch: [b][c][m]
__device__ __half g_p[(long)B_ * N_ * M_];       // unnormalized exp (128 MB)
__device__ float  g_partial[(long)R_ * 32];      // per (row, 128-coltile) exp sums
__device__ float  g_rinv[R_];                    // 1 / rowsum

// ---------------------------------------------------------------------------
// Conversion kernel
// ---------------------------------------------------------------------------
#define NIN (R_ * C_)
#define NV4 (NIN / 4)
#define WCNT (C_ * C_)

__global__ void __launch_bounds__(256) convert_all(
    const float* __restrict__ rgb, const float* __restrict__ dep,
    const float* __restrict__ Wq, const float* __restrict__ Wk,
    const float* __restrict__ Wv,
    __half* __restrict__ orgb, __half* __restrict__ odep,
    __half* __restrict__ owt)
{
    int i = blockIdx.x * blockDim.x + threadIdx.x;
    if (i < 2 * NV4) {
        const float4* src = (i < NV4) ? (const float4*)rgb : (const float4*)dep;
        __half* dst = (i < NV4) ? orgb : odep;
        int j = (i < NV4) ? i : i - NV4;
        float4 v = src[j];
        __half2 h0, h1;
        h0.x = __float2half_rn(v.x); h0.y = __float2half_rn(v.y);
        h1.x = __float2half_rn(v.z); h1.y = __float2half_rn(v.w);
        *(__half2*)(dst + j * 4)     = h0;
        *(__half2*)(dst + j * 4 + 2) = h1;
    } else {
        int j = i - 2 * NV4;
        if (j < 3 * WCNT) {
            const float* W = (j < WCNT) ? Wq : (j < 2 * WCNT) ? Wk : Wv;
            int t = (j < WCNT) ? j : (j < 2 * WCNT) ? j - WCNT : j - 2 * WCNT;
            int co = t >> 9, c = t & 511;
            owt[j] = __float2half_rn(W[c * C_ + co]);
        }
    }
}

// ---------------------------------------------------------------------------
// Rowsum reduce: 32 partials per row -> 1/sum
// ---------------------------------------------------------------------------
__global__ void rowsum_kernel(const float* __restrict__ partial,
                              float* __restrict__ rinv) {
    int i = blockIdx.x * blockDim.x + threadIdx.x;   // 0..R_-1
    const float4* p = (const float4*)(partial + (long)i * 32);
    float s = 0.f;
    #pragma unroll
    for (int j = 0; j < 8; j++) {
        float4 v = p[j];
        s += (v.x + v.y) + (v.z + v.w);
    }
    rinv[i] = 1.0f / s;
}

// ---------------------------------------------------------------------------
// Normalize: out[row][c] *= rinv[row]   (float4 vectorized)
// ---------------------------------------------------------------------------
__global__ void __launch_bounds__(256) normalize_k(float* __restrict__ out,
                                                   const float* __restrict__ rinv) {
    long i = (long)blockIdx.x * blockDim.x + threadIdx.x;   // over R_*C_/4
    float4* o4 = (float4*)out;
    int row = (int)(i / (C_ / 4));
    float r = rinv[row];
    float4 v = o4[i];
    v.x *= r; v.y *= r; v.z *= r; v.w *= r;
    o4[i] = v;
}

// ---------------------------------------------------------------------------
// Champion fp16 GEMM, templated epilogue.
// D[128x128] = sum_k A[rowtile,k] * B[coltile,k], both K-major.
// MODE 0: fused QKV projection; bz=0 -> Q (A=rgb), bz=1 -> K (A=dep),
//         bz=2 -> V^T (A=dep, transposed store); +bias
// MODE 2: scores -> P = exp2(S*scale2) fp16 + deterministic partial sums
// MODE 3: PV -> unnormalized O fp32
// ---------------------------------------------------------------------------
template <int MODE, int KTOT>
__global__ void __launch_bounds__(256, 2) gemm_f16(
    const __half* __restrict__ A0, const __half* __restrict__ A1,
    const __half* __restrict__ B0,
    const float* __restrict__ bias0, const float* __restrict__ bias1,
    const float* __restrict__ bias2,
    float scale2,
    __half* __restrict__ H0, __half* __restrict__ H1, __half* __restrict__ H2,
    float* __restrict__ outF, float* __restrict__ partial)
{
    extern __shared__ char smem[];
    const uint32_t sb = smem_u32(smem);
    const int tid = threadIdx.x, lane = tid & 31, wid = tid >> 5;
    const int wm = wid >> 2, wn = wid & 3;          // warp grid 2(M) x 4(N)
    const int bx = blockIdx.x, by = blockIdx.y, bz = blockIdx.z;

    constexpr int kIters = KTOT / BK;

    // ---- operand base pointers per mode
    const __half* Ap;
    const __half* Bq;
    if constexpr (MODE == 0) {
        Ap = (bz == 0) ? A0 : A1;                    // rgb for Q, dep for K/V
        Bq = B0 + (long)bz * WCNT;
    } else if constexpr (MODE == 2) {
        Ap = A0 + (long)bz * ((long)N_ * C_);
        Bq = B0 + (long)bz * ((long)M_ * C_);
    } else {
        Ap = A0 + (long)bz * NM_;
        Bq = B0 + (long)bz * ((long)C_ * M_);
    }

    // ---- cp.async assignment: thread -> (row, 64B half of a 128B row)
    const int lrow = tid >> 1;                       // 0..127
    const int lhalf = tid & 1;                       // 0/1 -> +0B / +64B
    const __half* pA = Ap + (long)(bx * 128 + lrow) * KTOT + lhalf * 32;
    const __half* pB = Bq + (long)(by * 128 + lrow) * KTOT + lhalf * 32;
    const uint32_t sst = sb + (uint32_t)lrow * ROWB + lhalf * 64;

    auto issue = [&](int kt, int stage) {
        const uint32_t s0 = sst + stage * STAGE_B;
        const int off = kt * BK;
        #pragma unroll
        for (int c = 0; c < 4; c++) {
            CP16(s0 + c * 16,          pA + off + c * 8);
            CP16(s0 + TILE_B + c * 16, pB + off + c * 8);
        }
    };

    float d[4][4][4];
    #pragma unroll
    for (int i = 0; i < 4; i++)
        #pragma unroll
        for (int j = 0; j < 4; j++)
            #pragma unroll
            for (int e = 0; e < 4; e++) d[i][j][e] = 0.f;

    issue(0, 0);
    CP_COMMIT();
    issue(1, 1);
    CP_COMMIT();

    for (int kt = 0; kt < kIters; kt++) {
        CP_WAIT(1);
        __syncthreads();
        if (kt + 2 < kIters) issue(kt + 2, (kt + 2) % STAGES);
        CP_COMMIT();

        const uint32_t st = sb + (kt % STAGES) * STAGE_B;
        #pragma unroll
        for (int s = 0; s < 4; s++) {                // four k16 steps per BK=64
            uint32_t ah[4][4], bh[4][2];
            const uint32_t coff = s * 32 + (lane >> 4) * 16;
            const uint32_t rowA = wm * 64 + (lane & 15);
            #pragma unroll
            for (int mt = 0; mt < 4; mt++)
                LDSM4(ah[mt], st + (rowA + mt * 16) * ROWB + coff);
            const uint32_t rowB = wn * 32 + (lane & 15);
            #pragma unroll
            for (int np = 0; np < 2; np++) {
                uint32_t r[4];
                LDSM4(r, st + TILE_B + (rowB + np * 16) * ROWB + coff);
                bh[2 * np][0] = r[0]; bh[2 * np][1] = r[2];
                bh[2 * np + 1][0] = r[1]; bh[2 * np + 1][1] = r[3];
            }
            #pragma unroll
            for (int mt = 0; mt < 4; mt++)
                #pragma unroll
                for (int nt = 0; nt < 4; nt++)
                    MMA(d[mt][nt], ah[mt], bh[nt][0], bh[nt][1]);
        }
    }

    // ---- epilogue
    const int mbase = bx * 128 + wm * 64;
    const int nbase = by * 128 + wn * 32;
    const int lr = lane >> 2;            // 0..7
    const int lc = (lane & 3) * 2;       // 0,2,4,6

    float esum[4][2];
    #pragma unroll
    for (int i = 0; i < 4; i++) { esum[i][0] = 0.f; esum[i][1] = 0.f; }

    #pragma unroll
    for (int mt = 0; mt < 4; mt++) {
        #pragma unroll
        for (int nt = 0; nt < 4; nt++) {
            #pragma unroll
            for (int h = 0; h < 2; h++) {
                const int m = mbase + mt * 16 + lr + h * 8;
                const int n = nbase + nt * 8 + lc;
                float v0 = d[mt][nt][h * 2 + 0];
                float v1 = d[mt][nt][h * 2 + 1];
                if constexpr (MODE == 0) {
                    const float* bias = (bz == 0) ? bias0 : (bz == 1) ? bias1 : bias2;
                    v0 += bias[n]; v1 += bias[n + 1];
                    if (bz < 2) {
                        __half* o = (bz == 0) ? H0 : H1;
                        __half2 hv;
                        hv.x = __float2half_rn(v0); hv.y = __float2half_rn(v1);
                        *(__half2*)(o + (long)m * C_ + n) = hv;
                    } else {
                        const int b = m >> 12, mm = m & 4095;
                        const long idx = (long)b * ((long)C_ * M_) + (long)n * M_ + mm;
                        H2[idx]      = __float2half_rn(v0);
                        H2[idx + M_] = __float2half_rn(v1);
                    }
                } else if constexpr (MODE == 2) {
                    float e0 = exp2f(v0 * scale2);
                    float e1 = exp2f(v1 * scale2);
                    esum[mt][h] += e0 + e1;
                    __half2 hv;
                    hv.x = __float2half_rn(e0); hv.y = __float2half_rn(e1);
                    *(__half2*)(H0 + (long)bz * NM_ + (long)m * M_ + n) = hv;
                } else {
                    const long idx = (long)bz * ((long)N_ * C_) + (long)m * C_ + n;
                    float2 v; v.x = v0; v.y = v1;
                    *(float2*)(outF + idx) = v;
                }
            }
        }
    }

    if constexpr (MODE == 2) {
        // deterministic partial row sums: quad shfl -> smem -> global
        CP_WAIT(0);
        __syncthreads();                 // mainloop smem traffic complete
        float* sred = (float*)smem;      // [4 warp-cols][128 rows]
        #pragma unroll
        for (int mt = 0; mt < 4; mt++) {
            #pragma unroll
            for (int h = 0; h < 2; h++) {
                float v = esum[mt][h];
                v += __shfl_xor_sync(0xFFFFFFFFu, v, 1);
                v += __shfl_xor_sync(0xFFFFFFFFu, v, 2);
                if ((lane & 3) == 0)
                    sred[wn * 128 + wm * 64 + mt * 16 + h * 8 + lr] = v;
            }
        }
        __syncthreads();
        if (tid < 128) {
            float s = sred[tid] + sred[128 + tid] + sred[256 + tid] + sred[384 + tid];
            partial[((long)(bz * N_ + bx * 128 + tid)) * 32 + by] = s;
        }
    }
}

// ---------------------------------------------------------------------------
// Host launch.  ncu captures launch #4 -> PV there:
//   1 convert, 2 projQKV(fused z=3), 3 scores, 4 PV (ncu), 5 rowsum, 6 normalize
// ---------------------------------------------------------------------------
extern "C" void kernel_launch(void* const* d_in, const int* in_sizes, int n_in,
                              void* d_out, int out_size) {
    (void)in_sizes; (void)n_in; (void)out_size;
    const float* rgb = (const float*)d_in[0];
    const float* dep = (const float*)d_in[1];
    const float* Wq  = (const float*)d_in[2];
    const float* bq  = (const float*)d_in[3];
    const float* Wk  = (const float*)d_in[4];
    const float* bk  = (const float*)d_in[5];
    const float* Wv  = (const float*)d_in[6];
    const float* bv  = (const float*)d_in[7];
    float* out = (float*)d_out;

    void* p;
    __half *rgb_h, *dep_h, *wt, *q, *k, *vt, *ph;
    float *partial, *rinv;
    cudaGetSymbolAddress(&p, g_rgb);     rgb_h   = (__half*)p;
    cudaGetSymbolAddress(&p, g_dep);     dep_h   = (__half*)p;
    cudaGetSymbolAddress(&p, g_wt);      wt      = (__half*)p;
    cudaGetSymbolAddress(&p, g_q);       q       = (__half*)p;
    cudaGetSymbolAddress(&p, g_k);       k       = (__half*)p;
    cudaGetSymbolAddress(&p, g_vt);      vt      = (__half*)p;
    cudaGetSymbolAddress(&p, g_p);       ph      = (__half*)p;
    cudaGetSymbolAddress(&p, g_partial); partial = (float*)p;
    cudaGetSymbolAddress(&p, g_rinv);    rinv    = (float*)p;

    cudaFuncSetAttribute((const void*)gemm_f16<0, 512>,
                         cudaFuncAttributeMaxDynamicSharedMemorySize, SMEM_B);
    cudaFuncSetAttribute((const void*)gemm_f16<2, 512>,
                         cudaFuncAttributeMaxDynamicSharedMemorySize, SMEM_B);
    cudaFuncSetAttribute((const void*)gemm_f16<3, 4096>,
                         cudaFuncAttributeMaxDynamicSharedMemorySize, SMEM_B);

    // Launch 1: conversions
    const int workItems = 2 * NV4 + 3 * WCNT;
    convert_all<<<(workItems + 255) / 256, 256>>>(rgb, dep, Wq, Wk, Wv,
                                                  rgb_h, dep_h, wt);

    // Launch 2: fused QKV projections (z selects Q/K/V)
    dim3 gProj(R_ / 128, C_ / 128, 3);   // (128, 4, 3)
    gemm_f16<0, 512><<<gProj, 256, SMEM_B>>>(rgb_h, dep_h, wt,
        bq, bk, bv, 0.f, q, k, vt, nullptr, nullptr);

    // Launch 3: scores + exp2.  scale2 = log2(e)/sqrt(C)
    dim3 gS(N_ / 128, M_ / 128, B_);   // (32, 32, 4)
    gemm_f16<2, 512><<<gS, 256, SMEM_B>>>(q, nullptr, k,
        nullptr, nullptr, nullptr, 0.06376237236133904f,
        ph, nullptr, nullptr, nullptr, partial);

    // Launch 4 (ncu target): PV unnormalized
    dim3 gO(N_ / 128, C_ / 128, B_);   // (32, 4, 4)
    gemm_f16<3, 4096><<<gO, 256, SMEM_B>>>(ph, nullptr, vt,
        nullptr, nullptr, nullptr, 0.f,
        nullptr, nullptr, nullptr, out, nullptr);

    // Launch 5: rowsum -> 1/sum
    rowsum_kernel<<<R_ / 256, 256>>>(partial, rinv);

    // Launch 6: normalize O by rinv
    normalize_k<<<(R_ * (C_ / 4)) / 256, 256>>>(out, rinv);
}

// round 17
// speedup vs baseline: 1.5895x; 1.5895x over previous
#include <cuda_runtime.h>
#include <cuda_fp16.h>
#include <cstdint>

// ---------------------------------------------------------------------------
// Problem constants
// ---------------------------------------------------------------------------
#define B_ 4
#define N_ 4096
#define M_ 4096
#define C_ 512
#define R_ (B_ * N_)                     // 16384 rows
static const long NM_ = (long)N_ * M_;   // 16,777,216 per batch

// ---------------------------------------------------------------------------
// Champion GEMM tiling (R7 = 831us): CTA 128x128, 8 warps (2Mx4N),
// warp tile 64x32, BK=64, 3-stage cp.async, 2 CTAs/SM.
// Ktot and mode are RUNTIME values: keeps the mainloop rolled (I-cache!)
// and exactly reproduces the champion's SASS shape.
// ---------------------------------------------------------------------------
#define BK 64
#define STAGES 3
#define ROWB 144                  // 64 fp16 = 128B + 16B pad (conflict-free)
#define TILE_B (128 * ROWB)       // 18432 B per operand tile
#define STAGE_B (2 * TILE_B)      // A, B
#define SMEM_B (STAGES * STAGE_B) // 110592 B

__device__ __forceinline__ uint32_t smem_u32(const void* p) {
    uint32_t a;
    asm("{ .reg .u64 t; cvta.to.shared.u64 t, %1; cvt.u32.u64 %0, t; }" : "=r"(a) : "l"(p));
    return a;
}

#define LDSM4(r, addr) \
    asm volatile("ldmatrix.sync.aligned.m8n8.x4.shared.b16 {%0,%1,%2,%3}, [%4];" \
                 : "=r"((r)[0]), "=r"((r)[1]), "=r"((r)[2]), "=r"((r)[3]) : "r"(addr))

#define MMA(dd, aa, b0, b1) \
    asm volatile("mma.sync.aligned.m16n8k16.row.col.f32.f16.f16.f32 " \
                 "{%0,%1,%2,%3}, {%4,%5,%6,%7}, {%8,%9}, {%0,%1,%2,%3};" \
                 : "+f"((dd)[0]), "+f"((dd)[1]), "+f"((dd)[2]), "+f"((dd)[3]) \
                 : "r"((aa)[0]), "r"((aa)[1]), "r"((aa)[2]), "r"((aa)[3]), \
                   "r"(b0), "r"(b1))

#define CP16(saddr, gptr) \
    asm volatile("cp.async.cg.shared.global [%0], [%1], 16;" :: "r"(saddr), "l"(gptr))

// ---------------------------------------------------------------------------
// Scratch
// ---------------------------------------------------------------------------
__device__ __half g_rgb[R_ * C_];
__device__ __half g_dep[R_ * C_];
__device__ __half g_wt[3 * C_ * C_];             // W^T for q,k,v: [co][c]
__device__ __half g_q[R_ * C_];
__device__ __half g_k[R_ * C_];
__device__ __half g_vt[(long)B_ * C_ * M_];      // V^T per batch: [b][c][m]
__device__ __half g_p[(long)B_ * N_ * M_];       // unnormalized exp (128 MB)
__device__ float  g_partial[(long)R_ * 32];      // per (row, 128-coltile) exp sums
__device__ float  g_rinv[R_];                    // 1 / rowsum

// ---------------------------------------------------------------------------
// Conversion kernel: rgb->fp16, dep->fp16, Wq/Wk/Wv -> W^T fp16
// ---------------------------------------------------------------------------
#define NIN (R_ * C_)
#define NV4 (NIN / 4)
#define WCNT (C_ * C_)

__global__ void __launch_bounds__(256) convert_all(
    const float* __restrict__ rgb, const float* __restrict__ dep,
    const float* __restrict__ Wq, const float* __restrict__ Wk,
    const float* __restrict__ Wv,
    __half* __restrict__ orgb, __half* __restrict__ odep,
    __half* __restrict__ owt)
{
    int i = blockIdx.x * blockDim.x + threadIdx.x;
    if (i < 2 * NV4) {
        const float4* src = (i < NV4) ? (const float4*)rgb : (const float4*)dep;
        __half* dst = (i < NV4) ? orgb : odep;
        int j = (i < NV4) ? i : i - NV4;
        float4 v = src[j];
        __half2 h0, h1;
        h0.x = __float2half_rn(v.x); h0.y = __float2half_rn(v.y);
        h1.x = __float2half_rn(v.z); h1.y = __float2half_rn(v.w);
        *(__half2*)(dst + j * 4)     = h0;
        *(__half2*)(dst + j * 4 + 2) = h1;
    } else {
        int j = i - 2 * NV4;
        if (j < 3 * WCNT) {
            const float* W = (j < WCNT) ? Wq : (j < 2 * WCNT) ? Wk : Wv;
            int t = (j < WCNT) ? j : (j < 2 * WCNT) ? j - WCNT : j - 2 * WCNT;
            int co = t >> 9, c = t & 511;
            owt[j] = __float2half_rn(W[c * C_ + co]);
        }
    }
}

// ---------------------------------------------------------------------------
// Rowsum reduce: 32 partials per row -> 1/sum
// ---------------------------------------------------------------------------
__global__ void rowsum_kernel(const float* __restrict__ partial,
                              float* __restrict__ rinv) {
    int i = blockIdx.x * blockDim.x + threadIdx.x;   // 0..R_-1
    const float4* p = (const float4*)(partial + (long)i * 32);
    float s = 0.f;
    #pragma unroll
    for (int j = 0; j < 8; j++) {
        float4 v = p[j];
        s += (v.x + v.y) + (v.z + v.w);
    }
    rinv[i] = 1.0f / s;
}

// ---------------------------------------------------------------------------
// Champion fp16 GEMM (R7 structure, runtime mode + Ktot).
// D[128x128] = sum_k A[rowtile,k] * B[coltile,k], both K-major.
//   mode 0: fused QKV projection. bz=0: Q (A=A0=rgb), bz=1: K (A=A1=dep),
//           bz=2: V^T (A=A1=dep, transposed store). +bias per bz.
//   mode 2: P = exp2(v*scale2) fp16, ld=M_, + deterministic partial sums
//   mode 3: out fp32 * rinv[row], ld=C_  (final output)
// ---------------------------------------------------------------------------
__global__ void __launch_bounds__(256, 2) gemm_f16(
    const __half* __restrict__ A0, const __half* __restrict__ A1,
    const __half* __restrict__ Bp,
    int Ktot, long aBatch, long bBatch,
    const float* __restrict__ bias0, const float* __restrict__ bias1,
    const float* __restrict__ bias2,
    float scale2, int mode,
    float* __restrict__ outF,
    __half* __restrict__ H0, __half* __restrict__ H1, __half* __restrict__ H2,
    float* __restrict__ partial, const float* __restrict__ rinv)
{
    extern __shared__ char smem[];
    const uint32_t sb = smem_u32(smem);
    const int tid = threadIdx.x, lane = tid & 31, wid = tid >> 5;
    const int wm = wid >> 2, wn = wid & 3;          // warp grid 2(M) x 4(N)
    const int bx = blockIdx.x, by = blockIdx.y, bz = blockIdx.z;

    // ---- operand base pointers (uniform, outside mainloop)
    const __half* Abase;
    const __half* Bbase;
    if (mode == 0) {
        Abase = (bz == 0) ? A0 : A1;                 // rgb for Q, dep for K/V
        Bbase = Bp + (long)bz * WCNT;
    } else {
        Abase = A0 + bz * aBatch;
        Bbase = Bp + bz * bBatch;
    }

    // ---- cp.async assignment: thread -> (row, 64B half of a 128B row)
    const int lrow = tid >> 1;                       // 0..127
    const int lhalf = tid & 1;                       // 0/1 -> +0B / +64B
    const __half* pA = Abase + (long)(bx * 128 + lrow) * Ktot + lhalf * 32;
    const __half* pB = Bbase + (long)(by * 128 + lrow) * Ktot + lhalf * 32;
    const uint32_t sst = sb + (uint32_t)lrow * ROWB + lhalf * 64;

    const int kIters = Ktot / BK;

    auto issue = [&](int kt, int stage) {
        const uint32_t s0 = sst + stage * STAGE_B;
        const int off = kt * BK;
        #pragma unroll
        for (int c = 0; c < 4; c++) {
            CP16(s0 + c * 16,          pA + off + c * 8);
            CP16(s0 + TILE_B + c * 16, pB + off + c * 8);
        }
    };

    float d[4][4][4];
    #pragma unroll
    for (int i = 0; i < 4; i++)
        #pragma unroll
        for (int j = 0; j < 4; j++)
            #pragma unroll
            for (int e = 0; e < 4; e++) d[i][j][e] = 0.f;

    issue(0, 0);
    asm volatile("cp.async.commit_group;" ::: "memory");
    issue(1, 1);
    asm volatile("cp.async.commit_group;" ::: "memory");

    for (int kt = 0; kt < kIters; kt++) {
        asm volatile("cp.async.wait_group 1;" ::: "memory");
        __syncthreads();
        if (kt + 2 < kIters) issue(kt + 2, (kt + 2) % STAGES);
        asm volatile("cp.async.commit_group;" ::: "memory");

        const uint32_t st = sb + (kt % STAGES) * STAGE_B;
        #pragma unroll
        for (int s = 0; s < 4; s++) {                // four k16 steps per BK=64
            uint32_t ah[4][4], bh[4][2];
            const uint32_t coff = s * 32 + (lane >> 4) * 16;
            const uint32_t rowA = wm * 64 + (lane & 15);
            #pragma unroll
            for (int mt = 0; mt < 4; mt++)
                LDSM4(ah[mt], st + (rowA + mt * 16) * ROWB + coff);
            const uint32_t rowB = wn * 32 + (lane & 15);
            #pragma unroll
            for (int np = 0; np < 2; np++) {
                uint32_t r[4];
                LDSM4(r, st + TILE_B + (rowB + np * 16) * ROWB + coff);
                bh[2 * np][0] = r[0]; bh[2 * np][1] = r[2];
                bh[2 * np + 1][0] = r[1]; bh[2 * np + 1][1] = r[3];
            }
            #pragma unroll
            for (int mt = 0; mt < 4; mt++)
                #pragma unroll
                for (int nt = 0; nt < 4; nt++)
                    MMA(d[mt][nt], ah[mt], bh[nt][0], bh[nt][1]);
        }
    }

    // ---- epilogue (registers only; smem reused for mode-2 reduction)
    const int mbase = bx * 128 + wm * 64;
    const int nbase = by * 128 + wn * 32;
    const int lr = lane >> 2;            // 0..7
    const int lc = (lane & 3) * 2;       // 0,2,4,6

    float esum[4][2];
    #pragma unroll
    for (int i = 0; i < 4; i++) { esum[i][0] = 0.f; esum[i][1] = 0.f; }

    #pragma unroll
    for (int mt = 0; mt < 4; mt++) {
        #pragma unroll
        for (int nt = 0; nt < 4; nt++) {
            #pragma unroll
            for (int h = 0; h < 2; h++) {
                const int m = mbase + mt * 16 + lr + h * 8;
                const int n = nbase + nt * 8 + lc;
                float v0 = d[mt][nt][h * 2 + 0];
                float v1 = d[mt][nt][h * 2 + 1];
                if (mode == 0) {
                    const float* bias = (bz == 0) ? bias0 : (bz == 1) ? bias1 : bias2;
                    v0 += bias[n]; v1 += bias[n + 1];
                    if (bz < 2) {
                        __half* o = (bz == 0) ? H0 : H1;
                        __half2 hv;
                        hv.x = __float2half_rn(v0); hv.y = __float2half_rn(v1);
                        *(__half2*)(o + (long)m * C_ + n) = hv;
                    } else {
                        const int b = m >> 12, mm = m & 4095;
                        const long idx = (long)b * ((long)C_ * M_) + (long)n * M_ + mm;
                        H2[idx]      = __float2half_rn(v0);
                        H2[idx + M_] = __float2half_rn(v1);
                    }
                } else if (mode == 2) {
                    float e0 = exp2f(v0 * scale2);
                    float e1 = exp2f(v1 * scale2);
                    esum[mt][h] += e0 + e1;
                    __half2 hv;
                    hv.x = __float2half_rn(e0); hv.y = __float2half_rn(e1);
                    *(__half2*)(H0 + (long)bz * NM_ + (long)m * M_ + n) = hv;
                } else {
                    const float r = rinv[bz * N_ + m];
                    const long idx = (long)bz * ((long)N_ * C_) + (long)m * C_ + n;
                    float2 v; v.x = v0 * r; v.y = v1 * r;
                    *(float2*)(outF + idx) = v;
                }
            }
        }
    }

    if (mode == 2) {
        // deterministic partial row sums: quad shfl -> smem -> global
        asm volatile("cp.async.wait_group 0;" ::: "memory");
        __syncthreads();                 // mainloop smem traffic complete
        float* sred = (float*)smem;      // [4 warp-cols][128 rows]
        #pragma unroll
        for (int mt = 0; mt < 4; mt++) {
            #pragma unroll
            for (int h = 0; h < 2; h++) {
                float v = esum[mt][h];
                v += __shfl_xor_sync(0xFFFFFFFFu, v, 1);
                v += __shfl_xor_sync(0xFFFFFFFFu, v, 2);
                if ((lane & 3) == 0)
                    sred[wn * 128 + wm * 64 + mt * 16 + h * 8 + lr] = v;
            }
        }
        __syncthreads();
        if (tid < 128) {
            float s = sred[tid] + sred[128 + tid] + sred[256 + tid] + sred[384 + tid];
            partial[((long)(bz * N_ + bx * 128 + tid)) * 32 + by] = s;
        }
    }
}

// ---------------------------------------------------------------------------
// Host launch: 1 convert, 2 projQKV (fused z=3), 3 scores, 4 rowsum, 5 PV
// ---------------------------------------------------------------------------
extern "C" void kernel_launch(void* const* d_in, const int* in_sizes, int n_in,
                              void* d_out, int out_size) {
    (void)in_sizes; (void)n_in; (void)out_size;
    const float* rgb = (const float*)d_in[0];
    const float* dep = (const float*)d_in[1];
    const float* Wq  = (const float*)d_in[2];
    const float* bq  = (const float*)d_in[3];
    const float* Wk  = (const float*)d_in[4];
    const float* bk  = (const float*)d_in[5];
    const float* Wv  = (const float*)d_in[6];
    const float* bv  = (const float*)d_in[7];
    float* out = (float*)d_out;

    void* p;
    __half *rgb_h, *dep_h, *wt, *q, *k, *vt, *ph;
    float *partial, *rinv;
    cudaGetSymbolAddress(&p, g_rgb);     rgb_h   = (__half*)p;
    cudaGetSymbolAddress(&p, g_dep);     dep_h   = (__half*)p;
    cudaGetSymbolAddress(&p, g_wt);      wt      = (__half*)p;
    cudaGetSymbolAddress(&p, g_q);       q       = (__half*)p;
    cudaGetSymbolAddress(&p, g_k);       k       = (__half*)p;
    cudaGetSymbolAddress(&p, g_vt);      vt      = (__half*)p;
    cudaGetSymbolAddress(&p, g_p);       ph      = (__half*)p;
    cudaGetSymbolAddress(&p, g_partial); partial = (float*)p;
    cudaGetSymbolAddress(&p, g_rinv);    rinv    = (float*)p;

    cudaFuncSetAttribute(gemm_f16, cudaFuncAttributeMaxDynamicSharedMemorySize, SMEM_B);

    // Launch 1: conversions
    const int workItems = 2 * NV4 + 3 * WCNT;
    convert_all<<<(workItems + 255) / 256, 256>>>(rgb, dep, Wq, Wk, Wv,
                                                  rgb_h, dep_h, wt);

    // Launch 2: fused QKV projections (z selects Q/K/V)
    dim3 gProj(R_ / 128, C_ / 128, 3);   // (128, 4, 3)
    gemm_f16<<<gProj, 256, SMEM_B>>>(rgb_h, dep_h, wt,
        C_, 0, 0, bq, bk, bv, 0.f, 0,
        nullptr, q, k, vt, nullptr, nullptr);

    // Launch 3: scores + exp2.  scale2 = log2(e)/sqrt(C)
    dim3 gS(N_ / 128, M_ / 128, B_);   // (32, 32, 4)
    gemm_f16<<<gS, 256, SMEM_B>>>(q, nullptr, k,
        C_, (long)N_ * C_, (long)M_ * C_, nullptr, nullptr, nullptr,
        0.06376237236133904f, 2,
        nullptr, ph, nullptr, nullptr, partial, nullptr);

    // Launch 4: rowsum -> 1/sum
    rowsum_kernel<<<R_ / 256, 256>>>(partial, rinv);

    // Launch 5: O = (P V) * rinv[row]
    dim3 gO(N_ / 128, C_ / 128, B_);   // (32, 4, 4)
    gemm_f16<<<gO, 256, SMEM_B>>>(ph, nullptr, vt,
        M_, NM_, (long)C_ * M_, nullptr, nullptr, nullptr, 0.f, 3,
        out, nullptr, nullptr, nullptr, nullptr, rinv);
}